// round 1
// baseline (speedup 1.0000x reference)
#include <cuda_runtime.h>
#include <cstdint>

#define NN     512   // nodes
#define FIN    256   // input features
#define HF     256   // heads * hidden
#define NH     8     // heads
#define NF     32    // hidden per head
#define NB     4     // batch
#define ITILE  16    // i-rows per CTA in attention kernel
#define GLS    33    // padded row stride for g_l tile (conflict-free lane-strided reads)
#define GRS    34    // padded row stride for g_r tile (even -> float2 aligned)

// scratch: g[b*512+n][c], c in [0,256) = g_l(h,f), c in [256,512) = g_r(h,f)
__device__ float g_scratch[(size_t)NB * NN * 512];

// ---------------------------------------------------------------------------
// Kernel 1: fused GEMM  g_l = h @ W_l, g_r = h @ W_r   (M=2048, K=256, N=256 x2)
// 64x64 tiles, BK=16, 256 threads, 4x4 microtile.
// grid.x: 0..3 -> W_l cols, 4..7 -> W_r cols ; grid.y: M tiles (32)
// ---------------------------------------------------------------------------
__global__ __launch_bounds__(256, 2)
void gemm_kernel(const float* __restrict__ A,
                 const float* __restrict__ WL,
                 const float* __restrict__ WR) {
    __shared__ float As[16][64];
    __shared__ float Bs[16][68];

    const int nb = blockIdx.x;                 // 0..7
    const float* Bm = (nb < 4) ? WL : WR;
    const int colOff = (nb < 4) ? 0 : 256;
    const int n0 = (nb & 3) * 64;
    const int m0 = blockIdx.y * 64;

    const int tid = threadIdx.x;
    const int tx = tid & 15;
    const int ty = tid >> 4;

    const int arow = tid >> 2;          // 0..63
    const int acol = (tid & 3) << 2;    // 0,4,8,12
    const int brow = tid >> 4;          // 0..15
    const int bcol = (tid & 15) << 2;   // 0..60

    float c[4][4] = {};

    for (int k0 = 0; k0 < FIN; k0 += 16) {
        float4 av = *(const float4*)(A  + (size_t)(m0 + arow) * FIN + k0 + acol);
        float4 bv = *(const float4*)(Bm + (size_t)(k0 + brow) * HF  + n0 + bcol);
        As[acol + 0][arow] = av.x;
        As[acol + 1][arow] = av.y;
        As[acol + 2][arow] = av.z;
        As[acol + 3][arow] = av.w;
        *(float4*)&Bs[brow][bcol] = bv;
        __syncthreads();

#pragma unroll
        for (int k = 0; k < 16; k++) {
            const float a0 = As[k][ty * 4 + 0];
            const float a1 = As[k][ty * 4 + 1];
            const float a2 = As[k][ty * 4 + 2];
            const float a3 = As[k][ty * 4 + 3];
            const float4 b4 = *(const float4*)&Bs[k][tx * 4];
            c[0][0] = fmaf(a0, b4.x, c[0][0]); c[0][1] = fmaf(a0, b4.y, c[0][1]);
            c[0][2] = fmaf(a0, b4.z, c[0][2]); c[0][3] = fmaf(a0, b4.w, c[0][3]);
            c[1][0] = fmaf(a1, b4.x, c[1][0]); c[1][1] = fmaf(a1, b4.y, c[1][1]);
            c[1][2] = fmaf(a1, b4.z, c[1][2]); c[1][3] = fmaf(a1, b4.w, c[1][3]);
            c[2][0] = fmaf(a2, b4.x, c[2][0]); c[2][1] = fmaf(a2, b4.y, c[2][1]);
            c[2][2] = fmaf(a2, b4.z, c[2][2]); c[2][3] = fmaf(a2, b4.w, c[2][3]);
            c[3][0] = fmaf(a3, b4.x, c[3][0]); c[3][1] = fmaf(a3, b4.y, c[3][1]);
            c[3][2] = fmaf(a3, b4.z, c[3][2]); c[3][3] = fmaf(a3, b4.w, c[3][3]);
        }
        __syncthreads();
    }

    float* C = g_scratch + (size_t)m0 * 512 + colOff + n0;
#pragma unroll
    for (int r = 0; r < 4; r++) {
        float4 v = make_float4(c[r][0], c[r][1], c[r][2], c[r][3]);
        *(float4*)(C + (size_t)(ty * 4 + r) * 512 + tx * 4) = v;
    }
}

// ---------------------------------------------------------------------------
// Kernel 2: fused GATv2 attention. One CTA = (b, h, 16 consecutive i).
// Stages g_l[b,:,h,:] and g_r[b,:,h,:] in smem. 8 warps x 2 i-rows each.
// Pass 1: scores + mask + softmax stats (normalization deferred).
// Pass 2: out[i,f] = (1/s_i) * sum_j p[i,j] * g_r[j,f]  (thread = (i, f-pair)).
// ---------------------------------------------------------------------------
#define SMEM_FLOATS (NN * GLS + NN * GRS + ITILE * NN + ITILE)
#define SMEM_BYTES  (SMEM_FLOATS * 4)

__global__ __launch_bounds__(256, 1)
void attn_kernel(const int* __restrict__ adj,
                 const float* __restrict__ attn_w,
                 float* __restrict__ out) {
    extern __shared__ float sm[];
    float* gl_s = sm;                       // [512][33]
    float* gr_s = sm + NN * GLS;            // [512][34]
    float* a_s  = gr_s + NN * GRS;          // [16][512]
    float* sinv = a_s + ITILE * NN;         // [16]

    const int b  = blockIdx.z;
    const int h  = blockIdx.y;
    const int i0 = blockIdx.x * ITILE;
    const int tid  = threadIdx.x;
    const int lane = tid & 31;
    const int warp = tid >> 5;

    // ---- stage g_l / g_r slices for this (b,h) into smem ----
    const float* gbase = g_scratch + ((size_t)b * NN) * 512 + h * NF;
    for (int idx = tid; idx < NN * 8; idx += 256) {
        const int j = idx >> 3;
        const int q = (idx & 7) << 2;
        const float* gp = gbase + (size_t)j * 512 + q;
        const float4 v = *(const float4*)gp;          // g_l chunk
        const float4 u = *(const float4*)(gp + 256);  // g_r chunk
        float* glr = gl_s + j * GLS + q;
        glr[0] = v.x; glr[1] = v.y; glr[2] = v.z; glr[3] = v.w;
        float* grr = gr_s + j * GRS + q;
        grr[0] = u.x; grr[1] = u.y; grr[2] = u.z; grr[3] = u.w;
    }

    float w[NF];
#pragma unroll
    for (int f = 0; f < NF; f++) w[f] = __ldg(attn_w + f);

    __syncthreads();

    // ---- pass 1: scores + mask + softmax stats (each warp: 2 i-rows) ----
    for (int ii = 0; ii < 2; ii++) {
        const int i_loc = warp * 2 + ii;
        const int i = i0 + i_loc;

        float gri[NF];
#pragma unroll
        for (int f = 0; f < NF; f++) gri[f] = gr_s[i * GRS + f];

        const int* adjrow = adj + (size_t)i * NN;
        float* arow = a_s + i_loc * NN;
        float m = -3.4e38f;

#pragma unroll 2
        for (int jj = 0; jj < 16; jj++) {
            const int j = (jj << 5) + lane;
            const float* glr = gl_s + j * GLS;   // lane stride 33 -> conflict-free
            float acc = 0.f;
#pragma unroll
            for (int f = 0; f < NF; f++) {
                const float x = glr[f] + gri[f];
                acc = fmaf(w[f], fmaxf(x, 0.21f * x), acc);   // leaky = max(x, 0.21x)
            }
            const float ev = adjrow[j] ? acc : -1000000.0f;
            arow[j] = ev;
            m = fmaxf(m, ev);
        }
#pragma unroll
        for (int o = 16; o; o >>= 1) m = fmaxf(m, __shfl_xor_sync(0xffffffffu, m, o));

        float s = 0.f;
#pragma unroll 4
        for (int jj = 0; jj < 16; jj++) {
            const int j = (jj << 5) + lane;
            const float p = __expf(arow[j] - m);
            arow[j] = p;
            s += p;
        }
#pragma unroll
        for (int o = 16; o; o >>= 1) s += __shfl_xor_sync(0xffffffffu, s, o);
        if (lane == 0) sinv[i_loc] = 1.0f / s;
    }
    __syncthreads();

    // ---- pass 2: out[i, f0:f0+2] = inv_i * sum_j p[i,j] * g_r[j, f0:f0+2] ----
    {
        const int i_loc = tid >> 4;            // 0..15
        const int f0 = (tid & 15) << 1;        // 0,2,..,30
        const float* arow = a_s + i_loc * NN;
        float o0 = 0.f, o1 = 0.f;
#pragma unroll 8
        for (int j = 0; j < NN; j++) {
            const float a = arow[j];                                 // 2-way broadcast
            const float2 gv = *(const float2*)(gr_s + j * GRS + f0); // conflict-free
            o0 = fmaf(a, gv.x, o0);
            o1 = fmaf(a, gv.y, o1);
        }
        const float inv = sinv[i_loc];
        const int i = i0 + i_loc;
        float2 ov = make_float2(o0 * inv, o1 * inv);
        *(float2*)(out + ((size_t)(b * NN + i)) * HF + h * NF + f0) = ov;
    }
}

// ---------------------------------------------------------------------------
extern "C" void kernel_launch(void* const* d_in, const int* in_sizes, int n_in,
                              void* d_out, int out_size) {
    (void)in_sizes; (void)n_in; (void)out_size;
    const float* h      = (const float*)d_in[0];
    const int*   adj    = (const int*)  d_in[1];
    const float* W_l    = (const float*)d_in[2];
    const float* W_r    = (const float*)d_in[3];
    const float* attn_w = (const float*)d_in[4];
    float* out = (float*)d_out;

    cudaFuncSetAttribute(attn_kernel,
                         cudaFuncAttributeMaxDynamicSharedMemorySize, SMEM_BYTES);

    dim3 gg(8, 32);
    gemm_kernel<<<gg, 256>>>(h, W_l, W_r);

    dim3 ag(NN / ITILE, NH, NB);
    attn_kernel<<<ag, 256, SMEM_BYTES>>>(adj, attn_w, out);
}

// round 2
// speedup vs baseline: 1.6300x; 1.6300x over previous
#include <cuda_runtime.h>
#include <cstdint>

#define NN     512   // nodes
#define FIN    256   // input features
#define HF     256   // heads * hidden
#define NH     8     // heads
#define NF     32    // hidden per head
#define NB     4     // batch
#define ITILE  16    // i-rows per CTA in attention kernel
#define GLS    36    // padded row stride (floats) for g_l tile: 16B aligned + conflict-free LDS.128
#define GRS    36    // same for g_r
#define ASTR   513   // padded row stride for score rows (multi-i loads conflict-free)

typedef unsigned long long ull;

__device__ float g_scratch[(size_t)NB * NN * 512];

// ---- packed f32x2 helpers -------------------------------------------------
__device__ __forceinline__ ull pack2(float lo, float hi) {
    ull r; asm("mov.b64 %0, {%1, %2};" : "=l"(r) : "f"(lo), "f"(hi)); return r;
}
__device__ __forceinline__ void unpack2(ull v, float& lo, float& hi) {
    asm("mov.b64 {%0, %1}, %2;" : "=f"(lo), "=f"(hi) : "l"(v));
}
__device__ __forceinline__ ull add2(ull a, ull b) {
    ull r; asm("add.rn.f32x2 %0, %1, %2;" : "=l"(r) : "l"(a), "l"(b)); return r;
}
__device__ __forceinline__ ull fma2(ull a, ull b, ull c) {
    ull r; asm("fma.rn.f32x2 %0, %1, %2, %3;" : "=l"(r) : "l"(a), "l"(b), "l"(c)); return r;
}
#define ABS2 0x7FFFFFFF7FFFFFFFULL

// ---------------------------------------------------------------------------
// Kernel 1: fused GEMM  g_l = h @ W_l, g_r = h @ W_r
// ---------------------------------------------------------------------------
__global__ __launch_bounds__(256, 2)
void gemm_kernel(const float* __restrict__ A,
                 const float* __restrict__ WL,
                 const float* __restrict__ WR) {
    __shared__ float As[16][64];
    __shared__ float Bs[16][68];

    const int nb = blockIdx.x;
    const float* Bm = (nb < 4) ? WL : WR;
    const int colOff = (nb < 4) ? 0 : 256;
    const int n0 = (nb & 3) * 64;
    const int m0 = blockIdx.y * 64;

    const int tid = threadIdx.x;
    const int tx = tid & 15;
    const int ty = tid >> 4;

    const int arow = tid >> 2;
    const int acol = (tid & 3) << 2;
    const int brow = tid >> 4;
    const int bcol = (tid & 15) << 2;

    float c[4][4] = {};

    for (int k0 = 0; k0 < FIN; k0 += 16) {
        float4 av = *(const float4*)(A  + (size_t)(m0 + arow) * FIN + k0 + acol);
        float4 bv = *(const float4*)(Bm + (size_t)(k0 + brow) * HF  + n0 + bcol);
        As[acol + 0][arow] = av.x;
        As[acol + 1][arow] = av.y;
        As[acol + 2][arow] = av.z;
        As[acol + 3][arow] = av.w;
        *(float4*)&Bs[brow][bcol] = bv;
        __syncthreads();

#pragma unroll
        for (int k = 0; k < 16; k++) {
            const float a0 = As[k][ty * 4 + 0];
            const float a1 = As[k][ty * 4 + 1];
            const float a2 = As[k][ty * 4 + 2];
            const float a3 = As[k][ty * 4 + 3];
            const float4 b4 = *(const float4*)&Bs[k][tx * 4];
            c[0][0] = fmaf(a0, b4.x, c[0][0]); c[0][1] = fmaf(a0, b4.y, c[0][1]);
            c[0][2] = fmaf(a0, b4.z, c[0][2]); c[0][3] = fmaf(a0, b4.w, c[0][3]);
            c[1][0] = fmaf(a1, b4.x, c[1][0]); c[1][1] = fmaf(a1, b4.y, c[1][1]);
            c[1][2] = fmaf(a1, b4.z, c[1][2]); c[1][3] = fmaf(a1, b4.w, c[1][3]);
            c[2][0] = fmaf(a2, b4.x, c[2][0]); c[2][1] = fmaf(a2, b4.y, c[2][1]);
            c[2][2] = fmaf(a2, b4.z, c[2][2]); c[2][3] = fmaf(a2, b4.w, c[2][3]);
            c[3][0] = fmaf(a3, b4.x, c[3][0]); c[3][1] = fmaf(a3, b4.y, c[3][1]);
            c[3][2] = fmaf(a3, b4.z, c[3][2]); c[3][3] = fmaf(a3, b4.w, c[3][3]);
        }
        __syncthreads();
    }

    float* C = g_scratch + (size_t)m0 * 512 + colOff + n0;
#pragma unroll
    for (int r = 0; r < 4; r++) {
        float4 v = make_float4(c[r][0], c[r][1], c[r][2], c[r][3]);
        *(float4*)(C + (size_t)(ty * 4 + r) * 512 + tx * 4) = v;
    }
}

// ---------------------------------------------------------------------------
// Kernel 2: fused GATv2 attention. CTA = (b, h, 16 i-rows).
//   e[i,j] = Sl[j] + Sr[i] + sum_f wb_f * |gl[j,f]+gr[i,f]|
//   (leaky(x) = 0.605 x + 0.395 |x|, wa = 0.605 w, wb = 0.395 w)
// ---------------------------------------------------------------------------
// smem layout (float offsets):
#define OFF_GL   0
#define OFF_GR   (NN * GLS)                    // 18432
#define OFF_AS   (OFF_GR + NN * GRS)           // 36864
#define OFF_SL   (OFF_AS + ITILE * ASTR)       // 45072
#define OFF_SINV (OFF_SL + NN)                 // 45584
#define OFF_SR   (OFF_SINV + 16)               // 45600
#define OFF_ADJ  (OFF_SR + 16)                 // 45616 (16B aligned)
#define SMEM_FLOATS (OFF_ADJ + ITILE * NN)     // 53808
#define SMEM_BYTES  (SMEM_FLOATS * 4)          // 215232

__global__ __launch_bounds__(256, 1)
void attn_kernel(const int* __restrict__ adj,
                 const float* __restrict__ attn_w,
                 float* __restrict__ out) {
    extern __shared__ float sm[];
    float* gl_s  = sm + OFF_GL;
    float* gr_s  = sm + OFF_GR;
    float* a_s   = sm + OFF_AS;
    float* Sl_s  = sm + OFF_SL;
    float* sinv  = sm + OFF_SINV;
    float* Sr_s  = sm + OFF_SR;
    int*   adj_s = (int*)(sm + OFF_ADJ);

    const int b  = blockIdx.z;
    const int h  = blockIdx.y;
    const int i0 = blockIdx.x * ITILE;
    const int tid  = threadIdx.x;
    const int lane = tid & 31;
    const int warp = tid >> 5;

    // ---- stage g_l / g_r / adj into smem ----
    const float* gbase = g_scratch + ((size_t)b * NN) * 512 + h * NF;
#pragma unroll
    for (int it = 0; it < 16; it++) {
        const int idx = it * 256 + tid;            // 0..4095
        const int j = idx >> 3;
        const int q = (idx & 7) << 2;
        const float* gp = gbase + (size_t)j * 512 + q;
        const float4 v = *(const float4*)gp;
        const float4 u = *(const float4*)(gp + 256);
        *(float4*)(gl_s + j * GLS + q) = v;
        *(float4*)(gr_s + j * GRS + q) = u;
    }
    {
        const int4* asrc = (const int4*)(adj + (size_t)i0 * NN);
#pragma unroll
        for (int it = 0; it < 8; it++) {
            const int idx = it * 256 + tid;        // 0..2047 int4 chunks
            ((int4*)adj_s)[idx] = asrc[idx];
        }
    }

    // build packed weights
    ull wa2[16], wb2[16];
#pragma unroll
    for (int p = 0; p < 16; p++) {
        const float w0 = __ldg(attn_w + 2 * p);
        const float w1 = __ldg(attn_w + 2 * p + 1);
        wa2[p] = pack2(0.605f * w0, 0.605f * w1);
        wb2[p] = pack2(0.395f * w0, 0.395f * w1);
    }
    __syncthreads();

    // ---- precompute Sl[j] (all j) and Sr[i] (this CTA's 16 rows) ----
    for (int j = tid; j < NN; j += 256) {
        const ull* glp = (const ull*)(gl_s + j * GLS);
        ull acc = 0;
#pragma unroll
        for (int p = 0; p < 16; p++) acc = fma2(wa2[p], glp[p], acc);
        float lo, hi; unpack2(acc, lo, hi);
        Sl_s[j] = lo + hi;
    }
    if (tid < 16) {
        const ull* grp = (const ull*)(gr_s + (i0 + tid) * GRS);
        ull acc = 0;
#pragma unroll
        for (int p = 0; p < 16; p++) acc = fma2(wa2[p], grp[p], acc);
        float lo, hi; unpack2(acc, lo, hi);
        Sr_s[tid] = lo + hi;
    }
    __syncthreads();

    // ---- pass 1: scores + mask (each warp: rows iA=2w, iB=2w+1) ----
    {
        const int ilA = warp * 2;
        const int ilB = ilA + 1;
        ull griA[16], griB[16];
        {
            const ull* ga = (const ull*)(gr_s + (i0 + ilA) * GRS);
            const ull* gb = (const ull*)(gr_s + (i0 + ilB) * GRS);
#pragma unroll
            for (int p = 0; p < 16; p++) { griA[p] = ga[p]; griB[p] = gb[p]; }
        }
        const float SrA = Sr_s[ilA];
        const float SrB = Sr_s[ilB];
        float* arowA = a_s + ilA * ASTR;
        float* arowB = a_s + ilB * ASTR;
        const int* adjA = adj_s + ilA * NN;
        const int* adjB = adj_s + ilB * NN;
        float mA = -3.4e38f, mB = -3.4e38f;

#pragma unroll 2
        for (int jj = 0; jj < 16; jj++) {
            const int j = (jj << 5) + lane;
            const ulonglong2* glp = (const ulonglong2*)(gl_s + j * GLS);
            ull aA0 = 0, aA1 = 0, aB0 = 0, aB1 = 0;
#pragma unroll
            for (int q = 0; q < 8; q++) {
                const ulonglong2 gv = glp[q];
                const int p0 = 2 * q, p1 = 2 * q + 1;
                ull sA0 = add2(gv.x, griA[p0]);
                ull sB0 = add2(gv.x, griB[p0]);
                ull sA1 = add2(gv.y, griA[p1]);
                ull sB1 = add2(gv.y, griB[p1]);
                aA0 = fma2(wb2[p0], sA0 & ABS2, aA0);
                aB0 = fma2(wb2[p0], sB0 & ABS2, aB0);
                aA1 = fma2(wb2[p1], sA1 & ABS2, aA1);
                aB1 = fma2(wb2[p1], sB1 & ABS2, aB1);
            }
            const float slj = Sl_s[j];
            float lA, hA, lB, hB;
            unpack2(add2(aA0, aA1), lA, hA);
            unpack2(add2(aB0, aB1), lB, hB);
            const float eA = slj + SrA + (lA + hA);
            const float eB = slj + SrB + (lB + hB);
            const float evA = adjA[j] ? eA : -1000000.0f;
            const float evB = adjB[j] ? eB : -1000000.0f;
            arowA[j] = evA;
            arowB[j] = evB;
            mA = fmaxf(mA, evA);
            mB = fmaxf(mB, evB);
        }
#pragma unroll
        for (int o = 16; o; o >>= 1) {
            mA = fmaxf(mA, __shfl_xor_sync(0xffffffffu, mA, o));
            mB = fmaxf(mB, __shfl_xor_sync(0xffffffffu, mB, o));
        }

        // exp + row sums
        float sA = 0.f, sB = 0.f;
#pragma unroll 4
        for (int jj = 0; jj < 16; jj++) {
            const int j = (jj << 5) + lane;
            const float pA = __expf(arowA[j] - mA);
            const float pB = __expf(arowB[j] - mB);
            arowA[j] = pA; arowB[j] = pB;
            sA += pA; sB += pB;
        }
#pragma unroll
        for (int o = 16; o; o >>= 1) {
            sA += __shfl_xor_sync(0xffffffffu, sA, o);
            sB += __shfl_xor_sync(0xffffffffu, sB, o);
        }
        if (lane == 0) { sinv[ilA] = 1.0f / sA; sinv[ilB] = 1.0f / sB; }
    }
    __syncthreads();

    // ---- pass 2: out[i,f] = inv_i * sum_j p[i,j] * g_r[j,f] ----
    // thread = (fq 0..7, ig 0..3, jq 0..7); warp == jq; thread covers 4 i, 4 f, 64 j
    {
        const int fq = tid & 7;
        const int ig = (tid >> 3) & 3;
        const int jq = tid >> 5;                   // == warp
        ull acc[4][2] = {};
        const int jbeg = jq * 64;
#pragma unroll 4
        for (int jo = 0; jo < 64; jo++) {
            const int j = jbeg + jo;
            const ulonglong2 gv = *(const ulonglong2*)(gr_s + j * GRS + fq * 4);
#pragma unroll
            for (int r = 0; r < 4; r++) {
                const float a = a_s[(ig * 4 + r) * ASTR + j];
                const ull a2 = pack2(a, a);
                acc[r][0] = fma2(a2, gv.x, acc[r][0]);
                acc[r][1] = fma2(a2, gv.y, acc[r][1]);
            }
        }
        // partials into gl_s (dead): part[jq][iloc][32f]
        float* part = gl_s;
#pragma unroll
        for (int r = 0; r < 4; r++) {
            const int off = ((jq * 16 + ig * 4 + r) << 5) + (fq << 2);
            *(ull*)(part + off)     = acc[r][0];
            *(ull*)(part + off + 2) = acc[r][1];
        }
    }
    __syncthreads();

    // ---- final reduce over 8 j-partials + scale + store ----
    {
        const int iloc = tid >> 4;
        const int f0 = (tid & 15) << 1;
        const float* part = gl_s;
        float s0 = 0.f, s1 = 0.f;
#pragma unroll
        for (int q = 0; q < 8; q++) {
            const float2 v = *(const float2*)(part + ((q * 16 + iloc) << 5) + f0);
            s0 += v.x; s1 += v.y;
        }
        const float inv = sinv[iloc];
        float2 ov = make_float2(s0 * inv, s1 * inv);
        *(float2*)(out + ((size_t)(b * NN + i0 + iloc)) * HF + h * NF + f0) = ov;
    }
}

// ---------------------------------------------------------------------------
extern "C" void kernel_launch(void* const* d_in, const int* in_sizes, int n_in,
                              void* d_out, int out_size) {
    (void)in_sizes; (void)n_in; (void)out_size;
    const float* h      = (const float*)d_in[0];
    const int*   adj    = (const int*)  d_in[1];
    const float* W_l    = (const float*)d_in[2];
    const float* W_r    = (const float*)d_in[3];
    const float* attn_w = (const float*)d_in[4];
    float* out = (float*)d_out;

    cudaFuncSetAttribute(attn_kernel,
                         cudaFuncAttributeMaxDynamicSharedMemorySize, SMEM_BYTES);

    dim3 gg(8, 32);
    gemm_kernel<<<gg, 256>>>(h, W_l, W_r);

    dim3 ag(NN / ITILE, NH, NB);
    attn_kernel<<<ag, 256, SMEM_BYTES>>>(adj, attn_w, out);
}